// round 10
// baseline (speedup 1.0000x reference)
#include <cuda_runtime.h>
#include <math.h>
#include <stdint.h>

#define N_HITS   16384
#define N_EDGES  262144
#define N_GROUPS 512
#define HID      128
#define HEADS    4
#define DH       32
#define LAYERS   3
#define EDGE_DIM 5
#define FFN_DIM  512
#define LN_EPS   1e-5f

// ---------------- scratch (static device globals; no allocation) ----------------
__device__ __align__(256) float g_h   [N_HITS * HID];
__device__ __align__(256) float g_qkv [N_HITS * 3 * HID];
__device__ __align__(256) float g_attn[N_HITS * HID];
__device__ __align__(256) float g_ffn [N_HITS * FFN_DIM];
__device__ int   g_deg [N_HITS];
__device__ int   g_rowptr[N_HITS + 1];
__device__ int   g_cursor[N_HITS];
__device__ int   g_esrc[N_EDGES];
__device__ float g_eattr[N_EDGES * EDGE_DIM];
__device__ float g_gmax[N_GROUPS * HID];
__device__ float g_gsum[2 * N_GROUPS * HID];
__device__ float g_cnt [3 * N_GROUPS];
__device__ __align__(256) float g_ge  [N_GROUPS * 2 * HID];
__device__ __align__(256) float g_Aaf [N_GROUPS * HID];
__device__ __align__(256) float g_Baf [N_GROUPS * HID];

// ---------------- helpers ----------------
__device__ __forceinline__ void atomicMaxFloat(float* addr, float value) {
    if (value >= 0.f)
        atomicMax((int*)addr, __float_as_int(value));
    else
        atomicMin((unsigned int*)addr, __float_as_uint(value));
}

__device__ __forceinline__ uint32_t smem_u32(const void* p) {
    uint32_t a;
    asm("{ .reg .u64 t; cvta.to.shared.u64 t, %1; cvt.u32.u64 %0, t; }" : "=r"(a) : "l"(p));
    return a;
}

__device__ __forceinline__ void bulk_g2s(uint32_t dst, const void* src, uint32_t bytes, uint32_t mbar) {
    asm volatile(
        "cp.async.bulk.shared::cluster.global.mbarrier::complete_tx::bytes [%0], [%1], %2, [%3];"
        :: "r"(dst), "l"(src), "r"(bytes), "r"(mbar) : "memory");
}

#define MBAR_INIT(addr, count) \
    asm volatile("mbarrier.init.shared.b64 [%0], %1;" :: "r"((uint32_t)(addr)), "r"((uint32_t)(count)) : "memory")
#define MBAR_EXPECT(addr, bytes) \
    asm volatile("mbarrier.arrive.expect_tx.shared.b64 _, [%0], %1;" :: "r"((uint32_t)(addr)), "r"((uint32_t)(bytes)) : "memory")

#define MBAR_WAIT(mbar_smem_addr, phase_parity) do { \
    uint32_t _mbar = (uint32_t)(mbar_smem_addr); \
    uint32_t _parity = (uint32_t)(phase_parity); \
    uint32_t _done; \
    asm volatile( \
        "{\n\t.reg .pred p;\n\t" \
        "mbarrier.try_wait.parity.acquire.cta.shared::cta.b64 p, [%1], %2;\n\t" \
        "selp.b32 %0, 1, 0, p;\n\t}" \
        : "=r"(_done) : "r"(_mbar), "r"(_parity) : "memory"); \
    if (!_done) { \
        asm volatile( \
            "{\n\t.reg .pred P1;\n\t" \
            "WAIT_LOOP_%=:\n\t" \
            "mbarrier.try_wait.parity.acquire.cta.shared::cta.b64 P1, [%0], %1, 0x989680;\n\t" \
            "@P1 bra.uni WAIT_DONE_%=;\n\t" \
            "bra.uni WAIT_LOOP_%=;\n\t" \
            "WAIT_DONE_%=:\n\t}" \
            :: "r"(_mbar), "r"(_parity) : "memory"); \
    } \
} while(0)

__device__ __forceinline__ void mma_tf32(float* d, const uint32_t* a, const uint32_t* b) {
    asm volatile(
        "mma.sync.aligned.m16n8k8.row.col.f32.tf32.tf32.f32 "
        "{%0,%1,%2,%3}, {%4,%5,%6,%7}, {%8,%9}, {%0,%1,%2,%3};"
        : "+f"(d[0]), "+f"(d[1]), "+f"(d[2]), "+f"(d[3])
        : "r"(a[0]), "r"(a[1]), "r"(a[2]), "r"(a[3]),
          "r"(b[0]), "r"(b[1]));
}

// ---------------- hist ----------------
__global__ void hist_kernel(const int* __restrict__ ei) {
    int e = blockIdx.x * blockDim.x + threadIdx.x;
    if (e < N_EDGES) atomicAdd(&g_deg[ei[N_EDGES + e]], 1);
}

// ---------------- single-block scan over 16384 degrees ----------------
__global__ void __launch_bounds__(1024) scan_kernel() {
    __shared__ int wsum[32];
    const int t = threadIdx.x;
    const int lane = t & 31;
    const int w = t >> 5;

    const int4* dp = (const int4*)g_deg;
    int4 a0 = dp[t * 4 + 0], a1 = dp[t * 4 + 1], a2 = dp[t * 4 + 2], a3 = dp[t * 4 + 3];
    int v[16] = {a0.x, a0.y, a0.z, a0.w, a1.x, a1.y, a1.z, a1.w,
                 a2.x, a2.y, a2.z, a2.w, a3.x, a3.y, a3.z, a3.w};
    int tot = 0;
    #pragma unroll
    for (int i = 0; i < 16; i++) { int tmp = v[i]; v[i] = tot; tot += tmp; }

    int x = tot;
    #pragma unroll
    for (int off = 1; off < 32; off <<= 1) {
        int y = __shfl_up_sync(0xffffffffu, x, off);
        if (lane >= off) x += y;
    }
    if (lane == 31) wsum[w] = x;
    __syncthreads();
    if (w == 0) {
        int s = wsum[lane];
        #pragma unroll
        for (int off = 1; off < 32; off <<= 1) {
            int y = __shfl_up_sync(0xffffffffu, s, off);
            if (lane >= off) s += y;
        }
        wsum[lane] = s;
    }
    __syncthreads();
    int base = (w ? wsum[w - 1] : 0) + (x - tot);
    int4 o[4];
    int* ov = (int*)o;
    #pragma unroll
    for (int i = 0; i < 16; i++) ov[i] = base + v[i];
    int4* rp = (int4*)g_rowptr;
    int4* cp = (int4*)g_cursor;
    #pragma unroll
    for (int i = 0; i < 4; i++) { rp[t * 4 + i] = o[i]; cp[t * 4 + i] = o[i]; }
    if (t == 0) g_rowptr[N_HITS] = wsum[31];
}

// ---------------- scatter: CSR order src + edge_attr copy ----------------
__global__ void scatter_kernel(const int* __restrict__ ei, const float* __restrict__ eattr) {
    int e = blockIdx.x * blockDim.x + threadIdx.x;
    if (e < N_EDGES) {
        int dstn = ei[N_EDGES + e];
        int pos = atomicAdd(&g_cursor[dstn], 1);
        g_esrc[pos] = ei[e];
        #pragma unroll
        for (int c = 0; c < EDGE_DIM; c++)
            g_eattr[pos * EDGE_DIM + c] = eattr[(size_t)e * EDGE_DIM + c];
    }
}

// ---------------- embed: h = x @ W(25x128) + b, plus all buffer zeroing ----------------
__global__ void __launch_bounds__(128) embed_kernel(
    const float* __restrict__ x, const float* __restrict__ W, const float* __restrict__ b)
{
    int gid = blockIdx.x * 128 + threadIdx.x;
    if (gid < N_HITS) g_deg[gid] = 0;
    if (gid < N_GROUPS * HID) g_gmax[gid] = -INFINITY;
    if (gid < 2 * N_GROUPS * HID) g_gsum[gid] = 0.f;
    if (gid < 3 * N_GROUPS) g_cnt[gid] = 0.f;

    __shared__ float sW[25 * 128];
    __shared__ float sx[8][25];
    int tid = threadIdx.x;
    for (int i = tid; i < 25 * 128; i += 128) sW[i] = W[i];
    int r0 = blockIdx.x * 8;
    for (int i = tid; i < 8 * 25; i += 128)
        sx[i / 25][i % 25] = x[(size_t)(r0 + i / 25) * 25 + (i % 25)];
    __syncthreads();
    float bb = b[tid];
    for (int r = 0; r < 8; r++) {
        float acc = bb;
        #pragma unroll
        for (int c = 0; c < 25; c++) acc = fmaf(sx[r][c], sW[c * 128 + tid], acc);
        g_h[(size_t)(r0 + r) * 128 + tid] = acc;
    }
}

// ---------------- TF32 GEMM: 64 x 128 x 32 tiles, 2-stage bulk-TMA, 3 CTAs/SM ----------------
// 256 threads, 8 warps (2 x 4), warp tile 32x32 via m16n8k8.
// mode 0: +bias (may be null)   mode 1: +bias, relu
// mode 2: out = LN(res + gemm + bias) * gam + bet   (requires N==128)
#define ASTRIDE 36
#define BSTRIDE 136
#define GBM 64
#define STG_A_BYTES (GBM * ASTRIDE * 4)
#define STG (STG_A_BYTES + 32 * BSTRIDE * 4)
#define GEMM_SMEM (64 + 2 * STG)

__global__ void __launch_bounds__(256, 3) gemm_kernel(
    const float* __restrict__ A, const float* __restrict__ B,
    const float* __restrict__ bias, float* __restrict__ C,
    int M, int N, int K, int mode,
    const float* __restrict__ res, const float* __restrict__ gam, const float* __restrict__ bet)
{
    constexpr int MT = GBM / 32;             // 2
    constexpr int NARR = GBM + 32;           // 96 producers

    extern __shared__ char sm[];
    const uint32_t sbase = smem_u32(sm);
    const uint32_t stg0 = sbase + 64;
    const int tid  = threadIdx.x;
    const int wid  = tid >> 5;
    const int lane = tid & 31;
    const int wm = wid & 1, wn = wid >> 1;
    const int g = lane >> 2, r = lane & 3;
    const int m0 = blockIdx.y * GBM;
    const int n0 = blockIdx.x * 128;
    const int nk = K >> 5;

    float acc[MT][4][4] = {};

    if (tid == 0) {
        MBAR_INIT(sbase +  0, NARR);
        MBAR_INIT(sbase + 16, NARR);
    }
    __syncthreads();

    auto produce = [&](int s, int slot) {
        const uint32_t mbar = sbase + slot * 16;
        const uint32_t dst = stg0 + slot * STG;
        if (tid < GBM) {
            MBAR_EXPECT(mbar, 128);
            bulk_g2s(dst + (uint32_t)(tid * ASTRIDE) * 4,
                     A + (size_t)(m0 + tid) * K + s * 32, 128, mbar);
        } else if (tid >= 128 && tid < 160) {
            int rowb = tid - 128;
            MBAR_EXPECT(mbar, 512);
            bulk_g2s(dst + STG_A_BYTES + (uint32_t)(rowb * BSTRIDE) * 4,
                     B + (size_t)(s * 32 + rowb) * N + n0, 512, mbar);
        }
    };

    produce(0, 0);
    produce(1, 1);

    for (int t = 0; t < nk; t++) {
        const int cs = t & 1;
        MBAR_WAIT(sbase + cs * 16, (t >> 1) & 1);

        const float* sA = (const float*)(sm + 64 + cs * STG);
        const float* sB = (const float*)(sm + 64 + cs * STG + STG_A_BYTES);
        #pragma unroll
        for (int ks = 0; ks < 4; ks++) {
            const int kk = ks * 8;
            uint32_t af[MT][4], bf[4][2];
            #pragma unroll
            for (int mt = 0; mt < MT; mt++) {
                int rb = wm * (MT * 16) + mt * 16;
                af[mt][0] = __float_as_uint(sA[(rb + g    ) * ASTRIDE + kk + r    ]);
                af[mt][1] = __float_as_uint(sA[(rb + g + 8) * ASTRIDE + kk + r    ]);
                af[mt][2] = __float_as_uint(sA[(rb + g    ) * ASTRIDE + kk + r + 4]);
                af[mt][3] = __float_as_uint(sA[(rb + g + 8) * ASTRIDE + kk + r + 4]);
            }
            #pragma unroll
            for (int nt = 0; nt < 4; nt++) {
                int cb = wn * 32 + nt * 8;
                bf[nt][0] = __float_as_uint(sB[(kk + r    ) * BSTRIDE + cb + g]);
                bf[nt][1] = __float_as_uint(sB[(kk + r + 4) * BSTRIDE + cb + g]);
            }
            #pragma unroll
            for (int mt = 0; mt < MT; mt++)
                #pragma unroll
                for (int nt = 0; nt < 4; nt++)
                    mma_tf32(acc[mt][nt], af[mt], bf[nt]);
        }

        __syncthreads();
        if (t + 2 < nk) produce(t + 2, cs);
    }

    if (mode < 2) {
        #pragma unroll
        for (int mt = 0; mt < MT; mt++) {
            int row_a = m0 + wm * (MT * 16) + mt * 16 + g;
            int row_b = row_a + 8;
            #pragma unroll
            for (int nt = 0; nt < 4; nt++) {
                int col = n0 + wn * 32 + nt * 8 + 2 * r;
                float b0 = 0.f, b1 = 0.f;
                if (bias) { b0 = bias[col]; b1 = bias[col + 1]; }
                float v0 = acc[mt][nt][0] + b0;
                float v1 = acc[mt][nt][1] + b1;
                float v2 = acc[mt][nt][2] + b0;
                float v3 = acc[mt][nt][3] + b1;
                if (mode == 1) {
                    v0 = fmaxf(v0, 0.f); v1 = fmaxf(v1, 0.f);
                    v2 = fmaxf(v2, 0.f); v3 = fmaxf(v3, 0.f);
                }
                *(float2*)&C[(size_t)row_a * N + col] = make_float2(v0, v1);
                *(float2*)&C[(size_t)row_b * N + col] = make_float2(v2, v3);
            }
        }
    } else {
        float* sC = (float*)(sm + 64);
        #pragma unroll
        for (int mt = 0; mt < MT; mt++) {
            int lr = wm * (MT * 16) + mt * 16 + g;
            #pragma unroll
            for (int nt = 0; nt < 4; nt++) {
                int lc = wn * 32 + nt * 8 + 2 * r;
                sC[lr * 132 + lc]           = acc[mt][nt][0];
                sC[lr * 132 + lc + 1]       = acc[mt][nt][1];
                sC[(lr + 8) * 132 + lc]     = acc[mt][nt][2];
                sC[(lr + 8) * 132 + lc + 1] = acc[mt][nt][3];
            }
        }
        __syncthreads();
        if (tid < GBM) {
            int row = m0 + tid;
            const float* rp = res + (size_t)row * 128;
            float sum = 0.f, sq = 0.f;
            #pragma unroll 8
            for (int c = 0; c < 32; c++) {
                float4 v  = *(float4*)&sC[tid * 132 + c * 4];
                float4 bb = *(const float4*)&bias[c * 4];
                float4 hh = *(const float4*)&rp[c * 4];
                v.x += bb.x + hh.x; v.y += bb.y + hh.y;
                v.z += bb.z + hh.z; v.w += bb.w + hh.w;
                *(float4*)&sC[tid * 132 + c * 4] = v;
                sum += v.x + v.y + v.z + v.w;
                sq  += v.x * v.x + v.y * v.y + v.z * v.z + v.w * v.w;
            }
            float mu = sum * (1.f / 128.f);
            float var = sq * (1.f / 128.f) - mu * mu;
            float rstd = rsqrtf(var + LN_EPS);
            float* op = C + (size_t)row * 128;
            #pragma unroll 8
            for (int c = 0; c < 32; c++) {
                float4 v  = *(float4*)&sC[tid * 132 + c * 4];
                float4 gm = *(const float4*)&gam[c * 4];
                float4 bt = *(const float4*)&bet[c * 4];
                float4 o;
                o.x = (v.x - mu) * rstd * gm.x + bt.x;
                o.y = (v.y - mu) * rstd * gm.y + bt.y;
                o.z = (v.z - mu) * rstd * gm.z + bt.z;
                o.w = (v.w - mu) * rstd * gm.w + bt.w;
                *(float4*)&op[c * 4] = o;
            }
        }
    }
}

// ---------------- edge attention: warp/node, 2-edge unrolled online softmax ----------------
__global__ void __launch_bounds__(256) attn_kernel(
    const float* __restrict__ We, const float* __restrict__ be)
{
    const int node = (blockIdx.x * 256 + threadIdx.x) >> 5;
    const int lane = threadIdx.x & 31;
    if (node >= N_HITS) return;

    const int d0 = 4 * lane;
    float Wer[EDGE_DIM][4], ber[4];
    #pragma unroll
    for (int c = 0; c < 4; c++) {
        ber[c] = be[d0 + c];
        #pragma unroll
        for (int cc = 0; cc < EDGE_DIM; cc++) Wer[cc][c] = We[cc * HID + d0 + c];
    }
    float4 q = *(const float4*)&g_qkv[(size_t)node * 384 + d0];

    float m = -INFINITY, s = 0.f;
    float acc[4] = {0.f, 0.f, 0.f, 0.f};

    const int beg = g_rowptr[node], end = g_rowptr[node + 1];
    const float scale = 0.17677669529663687f;

    int idx = beg;
    for (; idx + 2 <= end; idx += 2) {
        int src1 = g_esrc[idx];
        int src2 = g_esrc[idx + 1];
        float ea1[EDGE_DIM], ea2[EDGE_DIM];
        #pragma unroll
        for (int cc = 0; cc < EDGE_DIM; cc++) {
            ea1[cc] = g_eattr[idx * EDGE_DIM + cc];
            ea2[cc] = g_eattr[idx * EDGE_DIM + EDGE_DIM + cc];
        }
        float4 k1 = *(const float4*)&g_qkv[(size_t)src1 * 384 + 128 + d0];
        float4 v1 = *(const float4*)&g_qkv[(size_t)src1 * 384 + 256 + d0];
        float4 k2 = *(const float4*)&g_qkv[(size_t)src2 * 384 + 128 + d0];
        float4 v2 = *(const float4*)&g_qkv[(size_t)src2 * 384 + 256 + d0];

        float e1[4], e2[4];
        #pragma unroll
        for (int c = 0; c < 4; c++) {
            float t1 = ber[c], t2 = ber[c];
            #pragma unroll
            for (int cc = 0; cc < EDGE_DIM; cc++) {
                t1 = fmaf(ea1[cc], Wer[cc][c], t1);
                t2 = fmaf(ea2[cc], Wer[cc][c], t2);
            }
            e1[c] = t1; e2[c] = t2;
        }
        float d1 = q.x * (k1.x + e1[0]) + q.y * (k1.y + e1[1])
                 + q.z * (k1.z + e1[2]) + q.w * (k1.w + e1[3]);
        float d2 = q.x * (k2.x + e2[0]) + q.y * (k2.y + e2[1])
                 + q.z * (k2.z + e2[2]) + q.w * (k2.w + e2[3]);
        #pragma unroll
        for (int off = 1; off <= 4; off <<= 1) {
            d1 += __shfl_xor_sync(0xffffffffu, d1, off);
            d2 += __shfl_xor_sync(0xffffffffu, d2, off);
        }
        float l1 = d1 * scale, l2 = d2 * scale;
        float mn = fmaxf(m, fmaxf(l1, l2));
        float c0 = __expf(m - mn);
        float p1 = __expf(l1 - mn);
        float p2 = __expf(l2 - mn);
        s = s * c0 + p1 + p2;
        acc[0] = acc[0] * c0 + p1 * (v1.x + e1[0]) + p2 * (v2.x + e2[0]);
        acc[1] = acc[1] * c0 + p1 * (v1.y + e1[1]) + p2 * (v2.y + e2[1]);
        acc[2] = acc[2] * c0 + p1 * (v1.z + e1[2]) + p2 * (v2.z + e2[2]);
        acc[3] = acc[3] * c0 + p1 * (v1.w + e1[3]) + p2 * (v2.w + e2[3]);
        m = mn;
    }
    if (idx < end) {
        int src1 = g_esrc[idx];
        float ea1[EDGE_DIM];
        #pragma unroll
        for (int cc = 0; cc < EDGE_DIM; cc++) ea1[cc] = g_eattr[idx * EDGE_DIM + cc];
        float4 k1 = *(const float4*)&g_qkv[(size_t)src1 * 384 + 128 + d0];
        float4 v1 = *(const float4*)&g_qkv[(size_t)src1 * 384 + 256 + d0];
        float e1[4];
        #pragma unroll
        for (int c = 0; c < 4; c++) {
            float t1 = ber[c];
            #pragma unroll
            for (int cc = 0; cc < EDGE_DIM; cc++) t1 = fmaf(ea1[cc], Wer[cc][c], t1);
            e1[c] = t1;
        }
        float d1 = q.x * (k1.x + e1[0]) + q.y * (k1.y + e1[1])
                 + q.z * (k1.z + e1[2]) + q.w * (k1.w + e1[3]);
        #pragma unroll
        for (int off = 1; off <= 4; off <<= 1)
            d1 += __shfl_xor_sync(0xffffffffu, d1, off);
        float l1 = d1 * scale;
        float mn = fmaxf(m, l1);
        float c0 = __expf(m - mn);
        float p1 = __expf(l1 - mn);
        s = s * c0 + p1;
        acc[0] = acc[0] * c0 + p1 * (v1.x + e1[0]);
        acc[1] = acc[1] * c0 + p1 * (v1.y + e1[1]);
        acc[2] = acc[2] * c0 + p1 * (v1.z + e1[2]);
        acc[3] = acc[3] * c0 + p1 * (v1.w + e1[3]);
    }
    float inv = 1.f / fmaxf(s, 1e-9f);
    *(float4*)&g_attn[(size_t)node * 128 + d0] =
        make_float4(acc[0] * inv, acc[1] * inv, acc[2] * inv, acc[3] * inv);
}

// ---------------- group pooling ----------------
__global__ void __launch_bounds__(128) pool_scatter_kernel(
    const float* __restrict__ x, const int* __restrict__ grp)
{
    int hit = blockIdx.x;
    int d = threadIdx.x;
    int g = grp[hit];
    float val = g_h[(size_t)hit * 128 + d];
    atomicMaxFloat(&g_gmax[g * 128 + d], val);
    int view = (int)x[(size_t)hit * 25 + 3];
    if (view == 0 || view == 1)
        atomicAdd(&g_gsum[view * N_GROUPS * HID + g * 128 + d], val);
    if (d == 0) {
        atomicAdd(&g_cnt[2 * N_GROUPS + g], 1.f);
        if (view == 0 || view == 1) atomicAdd(&g_cnt[view * N_GROUPS + g], 1.f);
    }
}

__global__ void __launch_bounds__(128) pool_finalize_kernel() {
    int g = blockIdx.x;
    int d = threadIdx.x;
    float cx = g_cnt[g], cy = g_cnt[N_GROUPS + g], ca = g_cnt[2 * N_GROUPS + g];
    float sx = g_gsum[g * 128 + d];
    float sy = g_gsum[N_GROUPS * HID + g * 128 + d];
    float px = sx / fmaxf(cx, 1.f);
    float py = sy / fmaxf(cy, 1.f);
    float hx = (cx > 0.f) ? 1.f : 0.f;
    float hy = (cy > 0.f) ? 1.f : 0.f;
    float sum_feat = px * hx + py * hy;
    float valid = fmaxf(hx + hy, 1.f);
    g_ge[g * 256 + d] = sum_feat / valid;
    g_ge[g * 256 + 128 + d] = (ca > 0.f) ? g_gmax[g * 128 + d] : 0.f;
}

// ---------------- fused pairwise scores + symmetrize + sigmoid + mask ----------------
__global__ void __launch_bounds__(256) scores_final_kernel(
    const float* __restrict__ b1, const float* __restrict__ W2, const float* __restrict__ b2,
    const int* __restrict__ batch, float* __restrict__ out)
{
    __shared__ float sAi[16][129], sBj[16][129], sAj[16][129], sBi[16][129];
    __shared__ float sb1[128], sW2[128];
    __shared__ float s2s[16][17];

    int b = blockIdx.x;
    int bi = 0;
    while (b >= 32 - bi) { b -= 32 - bi; bi++; }
    int bj = bi + b;

    int tx = threadIdx.x & 15, ty = threadIdx.x >> 4;
    int tid = threadIdx.x;
    for (int t = tid; t < 16 * 128; t += 256) {
        int rr = t >> 7, cc = t & 127;
        sAi[rr][cc] = g_Aaf[(bi * 16 + rr) * 128 + cc];
        sAj[rr][cc] = g_Aaf[(bj * 16 + rr) * 128 + cc];
        sBi[rr][cc] = g_Baf[(bi * 16 + rr) * 128 + cc];
        sBj[rr][cc] = g_Baf[(bj * 16 + rr) * 128 + cc];
    }
    if (tid < 128) { sb1[tid] = b1[tid]; sW2[tid] = W2[tid]; }
    __syncthreads();

    float s1 = 0.f, s2 = 0.f;
    #pragma unroll 8
    for (int d = 0; d < 128; d++) {
        float w = sW2[d], bb = sb1[d];
        s1 = fmaf(fmaxf(sAi[ty][d] + sBj[tx][d] + bb, 0.f), w, s1);
        s2 = fmaf(fmaxf(sAj[ty][d] + sBi[tx][d] + bb, 0.f), w, s2);
    }
    s2s[ty][tx] = s2;
    __syncthreads();

    float sc = 0.5f * (s1 + s2s[tx][ty]) + b2[0];
    int i = bi * 16 + ty, j = bj * 16 + tx;
    float mask = (batch[i] == batch[j]) ? 1.f : 0.f;
    float val = mask / (1.f + expf(-sc));
    out[(size_t)i * N_GROUPS + j] = val;
    out[(size_t)j * N_GROUPS + i] = val;
}

// ---------------- launch ----------------
extern "C" void kernel_launch(void* const* d_in, const int* in_sizes, int n_in,
                              void* d_out, int out_size)
{
    const float* x          = (const float*)d_in[0];
    const int*   edge_index = (const int*)  d_in[1];
    const float* edge_attr  = (const float*)d_in[2];
    const int*   grp        = (const int*)  d_in[3];
    const int*   batch      = (const int*)  d_in[4];
    const float* embed_W    = (const float*)d_in[5];
    const float* embed_b    = (const float*)d_in[6];
    const float* Wqkv       = (const float*)d_in[7];
    const float* bqkv       = (const float*)d_in[8];
    const float* We         = (const float*)d_in[9];
    const float* be         = (const float*)d_in[10];
    const float* Wo         = (const float*)d_in[11];
    const float* bo         = (const float*)d_in[12];
    const float* ln1g       = (const float*)d_in[13];
    const float* ln1b       = (const float*)d_in[14];
    const float* W1         = (const float*)d_in[15];
    const float* b1         = (const float*)d_in[16];
    const float* W2         = (const float*)d_in[17];
    const float* b2         = (const float*)d_in[18];
    const float* ln2g       = (const float*)d_in[19];
    const float* ln2b       = (const float*)d_in[20];
    const float* affW1      = (const float*)d_in[21];
    const float* affb1      = (const float*)d_in[22];
    const float* affW2      = (const float*)d_in[23];
    const float* affb2      = (const float*)d_in[24];
    float* out = (float*)d_out;

    float *p_h, *p_qkv, *p_attn, *p_ffn, *p_ge, *p_A, *p_B;
    cudaGetSymbolAddress((void**)&p_h,    g_h);
    cudaGetSymbolAddress((void**)&p_qkv,  g_qkv);
    cudaGetSymbolAddress((void**)&p_attn, g_attn);
    cudaGetSymbolAddress((void**)&p_ffn,  g_ffn);
    cudaGetSymbolAddress((void**)&p_ge,   g_ge);
    cudaGetSymbolAddress((void**)&p_A,    g_Aaf);
    cudaGetSymbolAddress((void**)&p_B,    g_Baf);

    cudaFuncSetAttribute(gemm_kernel, cudaFuncAttributeMaxDynamicSharedMemorySize, GEMM_SMEM);

    // launch index 3 is the ncu-profiled slot -> qkv GEMM there
    embed_kernel<<<N_HITS / 8, 128>>>(x, embed_W, embed_b);                    // 0 (also zeroes buffers)
    hist_kernel<<<N_EDGES / 256, 256>>>(edge_index);                           // 1
    scan_kernel<<<1, 1024>>>();                                                // 2
    gemm_kernel<<<dim3(3, 256), 256, GEMM_SMEM>>>(                             // 3 (profiled)
        p_h, Wqkv, bqkv, p_qkv, N_HITS, 384, 128, 0, nullptr, nullptr, nullptr);
    scatter_kernel<<<N_EDGES / 256, 256>>>(edge_index, edge_attr);             // 4

    for (int l = 0; l < LAYERS; l++) {
        if (l > 0) {
            gemm_kernel<<<dim3(3, 256), 256, GEMM_SMEM>>>(
                p_h, Wqkv + (size_t)l * 49152, bqkv + l * 384, p_qkv,
                N_HITS, 384, 128, 0, nullptr, nullptr, nullptr);
        }
        attn_kernel<<<N_HITS / 8, 256>>>(We + (size_t)l * EDGE_DIM * HID, be + l * HID);
        // h = LN1(h + attn @ Wo + bo)
        gemm_kernel<<<dim3(1, 256), 256, GEMM_SMEM>>>(
            p_attn, Wo + (size_t)l * 16384, bo + l * 128, p_h,
            N_HITS, 128, 128, 2, p_h, ln1g + l * 128, ln1b + l * 128);
        // ffn = relu(h @ W1 + b1)
        gemm_kernel<<<dim3(4, 256), 256, GEMM_SMEM>>>(
            p_h, W1 + (size_t)l * 65536, b1 + l * 512, p_ffn,
            N_HITS, 512, 128, 1, nullptr, nullptr, nullptr);
        // h = LN2(h + ffn @ W2 + b2)
        gemm_kernel<<<dim3(1, 256), 256, GEMM_SMEM>>>(
            p_ffn, W2 + (size_t)l * 65536, b2 + l * 128, p_h,
            N_HITS, 128, 512, 2, p_h, ln2g + l * 128, ln2b + l * 128);
    }

    // pooling -> ge [512, 256]
    pool_scatter_kernel<<<N_HITS, 128>>>(x, grp);
    pool_finalize_kernel<<<N_GROUPS, 128>>>();

    // affinity projections: A = ge @ W1a, B = ge @ W1b
    gemm_kernel<<<dim3(1, 8), 256, GEMM_SMEM>>>(
        p_ge, affW1, nullptr, p_A, N_GROUPS, 128, 256, 0, nullptr, nullptr, nullptr);
    gemm_kernel<<<dim3(1, 8), 256, GEMM_SMEM>>>(
        p_ge, affW1 + (size_t)256 * 128, nullptr, p_B, N_GROUPS, 128, 256, 0, nullptr, nullptr, nullptr);

    // fused symmetric scores + sigmoid + mask
    scores_final_kernel<<<528, 256>>>(affb1, affW2, affb2, batch, out);
}

// round 13
// speedup vs baseline: 1.0894x; 1.0894x over previous
#include <cuda_runtime.h>
#include <math.h>
#include <stdint.h>

#define N_HITS   16384
#define N_EDGES  262144
#define N_GROUPS 512
#define HID      128
#define HEADS    4
#define DH       32
#define LAYERS   3
#define EDGE_DIM 5
#define FFN_DIM  512
#define LN_EPS   1e-5f

// ---------------- scratch (static device globals; no allocation) ----------------
__device__ __align__(256) float g_h   [N_HITS * HID];
__device__ __align__(256) float g_qkv [N_HITS * 3 * HID];
__device__ __align__(256) float g_attn[N_HITS * HID];
__device__ __align__(256) float g_ffn [N_HITS * FFN_DIM];
__device__ int   g_deg [N_HITS];
__device__ int   g_rowptr[N_HITS + 1];
__device__ int   g_cursor[N_HITS];
__device__ int   g_esrc[N_EDGES];
__device__ float g_eattr[N_EDGES * EDGE_DIM];
__device__ float g_gmax[N_GROUPS * HID];
__device__ float g_gsum[2 * N_GROUPS * HID];
__device__ float g_cnt [3 * N_GROUPS];
__device__ __align__(256) float g_ge  [N_GROUPS * 2 * HID];
__device__ __align__(256) float g_Aaf [N_GROUPS * HID];
__device__ __align__(256) float g_Baf [N_GROUPS * HID];

// ---------------- helpers ----------------
__device__ __forceinline__ void atomicMaxFloat(float* addr, float value) {
    if (value >= 0.f)
        atomicMax((int*)addr, __float_as_int(value));
    else
        atomicMin((unsigned int*)addr, __float_as_uint(value));
}

__device__ __forceinline__ uint32_t smem_u32(const void* p) {
    uint32_t a;
    asm("{ .reg .u64 t; cvta.to.shared.u64 t, %1; cvt.u32.u64 %0, t; }" : "=r"(a) : "l"(p));
    return a;
}

__device__ __forceinline__ void bulk_g2s(uint32_t dst, const void* src, uint32_t bytes, uint32_t mbar) {
    asm volatile(
        "cp.async.bulk.shared::cluster.global.mbarrier::complete_tx::bytes [%0], [%1], %2, [%3];"
        :: "r"(dst), "l"(src), "r"(bytes), "r"(mbar) : "memory");
}

#define MBAR_INIT(addr, count) \
    asm volatile("mbarrier.init.shared.b64 [%0], %1;" :: "r"((uint32_t)(addr)), "r"((uint32_t)(count)) : "memory")
#define MBAR_EXPECT(addr, bytes) \
    asm volatile("mbarrier.arrive.expect_tx.shared.b64 _, [%0], %1;" :: "r"((uint32_t)(addr)), "r"((uint32_t)(bytes)) : "memory")

#define MBAR_WAIT(mbar_smem_addr, phase_parity) do { \
    uint32_t _mbar = (uint32_t)(mbar_smem_addr); \
    uint32_t _parity = (uint32_t)(phase_parity); \
    uint32_t _done; \
    asm volatile( \
        "{\n\t.reg .pred p;\n\t" \
        "mbarrier.try_wait.parity.acquire.cta.shared::cta.b64 p, [%1], %2;\n\t" \
        "selp.b32 %0, 1, 0, p;\n\t}" \
        : "=r"(_done) : "r"(_mbar), "r"(_parity) : "memory"); \
    if (!_done) { \
        asm volatile( \
            "{\n\t.reg .pred P1;\n\t" \
            "WAIT_LOOP_%=:\n\t" \
            "mbarrier.try_wait.parity.acquire.cta.shared::cta.b64 P1, [%0], %1, 0x989680;\n\t" \
            "@P1 bra.uni WAIT_DONE_%=;\n\t" \
            "bra.uni WAIT_LOOP_%=;\n\t" \
            "WAIT_DONE_%=:\n\t}" \
            :: "r"(_mbar), "r"(_parity) : "memory"); \
    } \
} while(0)

__device__ __forceinline__ void mma_tf32(float* d, const uint32_t* a, const uint32_t* b) {
    asm volatile(
        "mma.sync.aligned.m16n8k8.row.col.f32.tf32.tf32.f32 "
        "{%0,%1,%2,%3}, {%4,%5,%6,%7}, {%8,%9}, {%0,%1,%2,%3};"
        : "+f"(d[0]), "+f"(d[1]), "+f"(d[2]), "+f"(d[3])
        : "r"(a[0]), "r"(a[1]), "r"(a[2]), "r"(a[3]),
          "r"(b[0]), "r"(b[1]));
}

// ---------------- hist ----------------
__global__ void hist_kernel(const int* __restrict__ ei) {
    int e = blockIdx.x * blockDim.x + threadIdx.x;
    if (e < N_EDGES) atomicAdd(&g_deg[ei[N_EDGES + e]], 1);
}

// ---------------- single-block scan over 16384 degrees ----------------
__global__ void __launch_bounds__(1024) scan_kernel() {
    __shared__ int wsum[32];
    const int t = threadIdx.x;
    const int lane = t & 31;
    const int w = t >> 5;

    const int4* dp = (const int4*)g_deg;
    int4 a0 = dp[t * 4 + 0], a1 = dp[t * 4 + 1], a2 = dp[t * 4 + 2], a3 = dp[t * 4 + 3];
    int v[16] = {a0.x, a0.y, a0.z, a0.w, a1.x, a1.y, a1.z, a1.w,
                 a2.x, a2.y, a2.z, a2.w, a3.x, a3.y, a3.z, a3.w};
    int tot = 0;
    #pragma unroll
    for (int i = 0; i < 16; i++) { int tmp = v[i]; v[i] = tot; tot += tmp; }

    int x = tot;
    #pragma unroll
    for (int off = 1; off < 32; off <<= 1) {
        int y = __shfl_up_sync(0xffffffffu, x, off);
        if (lane >= off) x += y;
    }
    if (lane == 31) wsum[w] = x;
    __syncthreads();
    if (w == 0) {
        int s = wsum[lane];
        #pragma unroll
        for (int off = 1; off < 32; off <<= 1) {
            int y = __shfl_up_sync(0xffffffffu, s, off);
            if (lane >= off) s += y;
        }
        wsum[lane] = s;
    }
    __syncthreads();
    int base = (w ? wsum[w - 1] : 0) + (x - tot);
    int4 o[4];
    int* ov = (int*)o;
    #pragma unroll
    for (int i = 0; i < 16; i++) ov[i] = base + v[i];
    int4* rp = (int4*)g_rowptr;
    int4* cp = (int4*)g_cursor;
    #pragma unroll
    for (int i = 0; i < 4; i++) { rp[t * 4 + i] = o[i]; cp[t * 4 + i] = o[i]; }
    if (t == 0) g_rowptr[N_HITS] = wsum[31];
}

// ---------------- scatter: CSR order src + edge_attr copy ----------------
__global__ void scatter_kernel(const int* __restrict__ ei, const float* __restrict__ eattr) {
    int e = blockIdx.x * blockDim.x + threadIdx.x;
    if (e < N_EDGES) {
        int dstn = ei[N_EDGES + e];
        int pos = atomicAdd(&g_cursor[dstn], 1);
        g_esrc[pos] = ei[e];
        #pragma unroll
        for (int c = 0; c < EDGE_DIM; c++)
            g_eattr[pos * EDGE_DIM + c] = eattr[(size_t)e * EDGE_DIM + c];
    }
}

// ---------------- embed: h = x @ W(25x128) + b, plus all buffer zeroing ----------------
__global__ void __launch_bounds__(128) embed_kernel(
    const float* __restrict__ x, const float* __restrict__ W, const float* __restrict__ b)
{
    int gid = blockIdx.x * 128 + threadIdx.x;
    if (gid < N_HITS) g_deg[gid] = 0;
    if (gid < N_GROUPS * HID) g_gmax[gid] = -INFINITY;
    if (gid < 2 * N_GROUPS * HID) g_gsum[gid] = 0.f;
    if (gid < 3 * N_GROUPS) g_cnt[gid] = 0.f;

    __shared__ float sW[25 * 128];
    __shared__ float sx[8][25];
    int tid = threadIdx.x;
    for (int i = tid; i < 25 * 128; i += 128) sW[i] = W[i];
    int r0 = blockIdx.x * 8;
    for (int i = tid; i < 8 * 25; i += 128)
        sx[i / 25][i % 25] = x[(size_t)(r0 + i / 25) * 25 + (i % 25)];
    __syncthreads();
    float bb = b[tid];
    for (int r = 0; r < 8; r++) {
        float acc = bb;
        #pragma unroll
        for (int c = 0; c < 25; c++) acc = fmaf(sx[r][c], sW[c * 128 + tid], acc);
        g_h[(size_t)(r0 + r) * 128 + tid] = acc;
    }
}

// ---------------- TF32 GEMM: 64 x 128 x 64 tiles, 2-stage bulk-TMA, 2 CTAs/SM ----------------
// 256 threads, 8 warps (2 x 4), warp tile 32x32 via m16n8k8. BK=64 halves loop overhead.
// mode 0: +bias (may be null)   mode 1: +bias, relu
// mode 2: out = LN(res + gemm + bias) * gam + bet   (requires N==128)
#define ASTRIDE 68
#define BSTRIDE 136
#define GBM 64
#define GBK 64
#define STG_A_BYTES (GBM * ASTRIDE * 4)
#define STG (STG_A_BYTES + GBK * BSTRIDE * 4)
#define STAGE_TX (GBM * GBK * 4 + GBK * 128 * 4)
#define GEMM_SMEM (64 + 2 * STG)

__global__ void __launch_bounds__(256, 2) gemm_kernel(
    const float* __restrict__ A, const float* __restrict__ B,
    const float* __restrict__ bias, float* __restrict__ C,
    int M, int N, int K, int mode,
    const float* __restrict__ res, const float* __restrict__ gam, const float* __restrict__ bet)
{
    constexpr int MT = GBM / 32;             // 2
    constexpr int NARR = 128;                // 64 A producers + 64 B producers

    extern __shared__ char sm[];
    const uint32_t sbase = smem_u32(sm);
    const uint32_t stg0 = sbase + 64;
    const int tid  = threadIdx.x;
    const int wid  = tid >> 5;
    const int lane = tid & 31;
    const int wm = wid & 1, wn = wid >> 1;
    const int g = lane >> 2, r = lane & 3;
    const int m0 = blockIdx.y * GBM;
    const int n0 = blockIdx.x * 128;
    const int nk = K >> 6;                   // K multiple of 64 for all uses

    float acc[MT][4][4] = {};

    if (tid == 0) {
        MBAR_INIT(sbase +  0, NARR);
        MBAR_INIT(sbase + 16, NARR);
    }
    __syncthreads();

    // A: 64 rows x 256B; B: 64 rows x 512B
    auto produce = [&](int s, int slot) {
        const uint32_t mbar = sbase + slot * 16;
        const uint32_t dst = stg0 + slot * STG;
        if (tid < GBM) {
            MBAR_EXPECT(mbar, 256);
            bulk_g2s(dst + (uint32_t)(tid * ASTRIDE) * 4,
                     A + (size_t)(m0 + tid) * K + s * GBK, 256, mbar);
        } else if (tid >= 128 && tid < 128 + GBK) {
            int rowb = tid - 128;
            MBAR_EXPECT(mbar, 512);
            bulk_g2s(dst + STG_A_BYTES + (uint32_t)(rowb * BSTRIDE) * 4,
                     B + (size_t)(s * GBK + rowb) * N + n0, 512, mbar);
        }
    };

    produce(0, 0);
    if (nk > 1) produce(1, 1);

    for (int t = 0; t < nk; t++) {
        const int cs = t & 1;
        MBAR_WAIT(sbase + cs * 16, (t >> 1) & 1);

        const float* sA = (const float*)(sm + 64 + cs * STG);
        const float* sB = (const float*)(sm + 64 + cs * STG + STG_A_BYTES);
        #pragma unroll
        for (int ks = 0; ks < 8; ks++) {
            const int kk = ks * 8;
            uint32_t af[MT][4], bf[4][2];
            #pragma unroll
            for (int mt = 0; mt < MT; mt++) {
                int rb = wm * (MT * 16) + mt * 16;
                af[mt][0] = __float_as_uint(sA[(rb + g    ) * ASTRIDE + kk + r    ]);
                af[mt][1] = __float_as_uint(sA[(rb + g + 8) * ASTRIDE + kk + r    ]);
                af[mt][2] = __float_as_uint(sA[(rb + g    ) * ASTRIDE + kk + r + 4]);
                af[mt][3] = __float_as_uint(sA[(rb + g + 8) * ASTRIDE + kk + r + 4]);
            }
            #pragma unroll
            for (int nt = 0; nt < 4; nt++) {
                int cb = wn * 32 + nt * 8;
                bf[nt][0] = __float_as_uint(sB[(kk + r    ) * BSTRIDE + cb + g]);
                bf[nt][1] = __float_as_uint(sB[(kk + r + 4) * BSTRIDE + cb + g]);
            }
            #pragma unroll
            for (int mt = 0; mt < MT; mt++)
                #pragma unroll
                for (int nt = 0; nt < 4; nt++)
                    mma_tf32(acc[mt][nt], af[mt], bf[nt]);
        }

        __syncthreads();
        if (t + 2 < nk) produce(t + 2, cs);
    }

    if (mode < 2) {
        #pragma unroll
        for (int mt = 0; mt < MT; mt++) {
            int row_a = m0 + wm * (MT * 16) + mt * 16 + g;
            int row_b = row_a + 8;
            #pragma unroll
            for (int nt = 0; nt < 4; nt++) {
                int col = n0 + wn * 32 + nt * 8 + 2 * r;
                float b0 = 0.f, b1 = 0.f;
                if (bias) { b0 = bias[col]; b1 = bias[col + 1]; }
                float v0 = acc[mt][nt][0] + b0;
                float v1 = acc[mt][nt][1] + b1;
                float v2 = acc[mt][nt][2] + b0;
                float v3 = acc[mt][nt][3] + b1;
                if (mode == 1) {
                    v0 = fmaxf(v0, 0.f); v1 = fmaxf(v1, 0.f);
                    v2 = fmaxf(v2, 0.f); v3 = fmaxf(v3, 0.f);
                }
                *(float2*)&C[(size_t)row_a * N + col] = make_float2(v0, v1);
                *(float2*)&C[(size_t)row_b * N + col] = make_float2(v2, v3);
            }
        }
    } else {
        float* sC = (float*)(sm + 64);
        #pragma unroll
        for (int mt = 0; mt < MT; mt++) {
            int lr = wm * (MT * 16) + mt * 16 + g;
            #pragma unroll
            for (int nt = 0; nt < 4; nt++) {
                int lc = wn * 32 + nt * 8 + 2 * r;
                sC[lr * 132 + lc]           = acc[mt][nt][0];
                sC[lr * 132 + lc + 1]       = acc[mt][nt][1];
                sC[(lr + 8) * 132 + lc]     = acc[mt][nt][2];
                sC[(lr + 8) * 132 + lc + 1] = acc[mt][nt][3];
            }
        }
        __syncthreads();
        if (tid < GBM) {
            int row = m0 + tid;
            const float* rp = res + (size_t)row * 128;
            float sum = 0.f, sq = 0.f;
            #pragma unroll 8
            for (int c = 0; c < 32; c++) {
                float4 v  = *(float4*)&sC[tid * 132 + c * 4];
                float4 bb = *(const float4*)&bias[c * 4];
                float4 hh = *(const float4*)&rp[c * 4];
                v.x += bb.x + hh.x; v.y += bb.y + hh.y;
                v.z += bb.z + hh.z; v.w += bb.w + hh.w;
                *(float4*)&sC[tid * 132 + c * 4] = v;
                sum += v.x + v.y + v.z + v.w;
                sq  += v.x * v.x + v.y * v.y + v.z * v.z + v.w * v.w;
            }
            float mu = sum * (1.f / 128.f);
            float var = sq * (1.f / 128.f) - mu * mu;
            float rstd = rsqrtf(var + LN_EPS);
            float* op = C + (size_t)row * 128;
            #pragma unroll 8
            for (int c = 0; c < 32; c++) {
                float4 v  = *(float4*)&sC[tid * 132 + c * 4];
                float4 gm = *(const float4*)&gam[c * 4];
                float4 bt = *(const float4*)&bet[c * 4];
                float4 o;
                o.x = (v.x - mu) * rstd * gm.x + bt.x;
                o.y = (v.y - mu) * rstd * gm.y + bt.y;
                o.z = (v.z - mu) * rstd * gm.z + bt.z;
                o.w = (v.w - mu) * rstd * gm.w + bt.w;
                *(float4*)&op[c * 4] = o;
            }
        }
    }
}

// ---------------- edge attention: warp/node, 2-edge unrolled online softmax ----------------
__global__ void __launch_bounds__(256) attn_kernel(
    const float* __restrict__ We, const float* __restrict__ be)
{
    const int node = (blockIdx.x * 256 + threadIdx.x) >> 5;
    const int lane = threadIdx.x & 31;
    if (node >= N_HITS) return;

    const int d0 = 4 * lane;
    float Wer[EDGE_DIM][4], ber[4];
    #pragma unroll
    for (int c = 0; c < 4; c++) {
        ber[c] = be[d0 + c];
        #pragma unroll
        for (int cc = 0; cc < EDGE_DIM; cc++) Wer[cc][c] = We[cc * HID + d0 + c];
    }
    float4 q = *(const float4*)&g_qkv[(size_t)node * 384 + d0];

    float m = -INFINITY, s = 0.f;
    float acc[4] = {0.f, 0.f, 0.f, 0.f};

    const int beg = g_rowptr[node], end = g_rowptr[node + 1];
    const float scale = 0.17677669529663687f;

    int idx = beg;
    for (; idx + 2 <= end; idx += 2) {
        int src1 = g_esrc[idx];
        int src2 = g_esrc[idx + 1];
        float ea1[EDGE_DIM], ea2[EDGE_DIM];
        #pragma unroll
        for (int cc = 0; cc < EDGE_DIM; cc++) {
            ea1[cc] = g_eattr[idx * EDGE_DIM + cc];
            ea2[cc] = g_eattr[idx * EDGE_DIM + EDGE_DIM + cc];
        }
        float4 k1 = *(const float4*)&g_qkv[(size_t)src1 * 384 + 128 + d0];
        float4 v1 = *(const float4*)&g_qkv[(size_t)src1 * 384 + 256 + d0];
        float4 k2 = *(const float4*)&g_qkv[(size_t)src2 * 384 + 128 + d0];
        float4 v2 = *(const float4*)&g_qkv[(size_t)src2 * 384 + 256 + d0];

        float e1[4], e2[4];
        #pragma unroll
        for (int c = 0; c < 4; c++) {
            float t1 = ber[c], t2 = ber[c];
            #pragma unroll
            for (int cc = 0; cc < EDGE_DIM; cc++) {
                t1 = fmaf(ea1[cc], Wer[cc][c], t1);
                t2 = fmaf(ea2[cc], Wer[cc][c], t2);
            }
            e1[c] = t1; e2[c] = t2;
        }
        float d1 = q.x * (k1.x + e1[0]) + q.y * (k1.y + e1[1])
                 + q.z * (k1.z + e1[2]) + q.w * (k1.w + e1[3]);
        float d2 = q.x * (k2.x + e2[0]) + q.y * (k2.y + e2[1])
                 + q.z * (k2.z + e2[2]) + q.w * (k2.w + e2[3]);
        #pragma unroll
        for (int off = 1; off <= 4; off <<= 1) {
            d1 += __shfl_xor_sync(0xffffffffu, d1, off);
            d2 += __shfl_xor_sync(0xffffffffu, d2, off);
        }
        float l1 = d1 * scale, l2 = d2 * scale;
        float mn = fmaxf(m, fmaxf(l1, l2));
        float c0 = __expf(m - mn);
        float p1 = __expf(l1 - mn);
        float p2 = __expf(l2 - mn);
        s = s * c0 + p1 + p2;
        acc[0] = acc[0] * c0 + p1 * (v1.x + e1[0]) + p2 * (v2.x + e2[0]);
        acc[1] = acc[1] * c0 + p1 * (v1.y + e1[1]) + p2 * (v2.y + e2[1]);
        acc[2] = acc[2] * c0 + p1 * (v1.z + e1[2]) + p2 * (v2.z + e2[2]);
        acc[3] = acc[3] * c0 + p1 * (v1.w + e1[3]) + p2 * (v2.w + e2[3]);
        m = mn;
    }
    if (idx < end) {
        int src1 = g_esrc[idx];
        float ea1[EDGE_DIM];
        #pragma unroll
        for (int cc = 0; cc < EDGE_DIM; cc++) ea1[cc] = g_eattr[idx * EDGE_DIM + cc];
        float4 k1 = *(const float4*)&g_qkv[(size_t)src1 * 384 + 128 + d0];
        float4 v1 = *(const float4*)&g_qkv[(size_t)src1 * 384 + 256 + d0];
        float e1[4];
        #pragma unroll
        for (int c = 0; c < 4; c++) {
            float t1 = ber[c];
            #pragma unroll
            for (int cc = 0; cc < EDGE_DIM; cc++) t1 = fmaf(ea1[cc], Wer[cc][c], t1);
            e1[c] = t1;
        }
        float d1 = q.x * (k1.x + e1[0]) + q.y * (k1.y + e1[1])
                 + q.z * (k1.z + e1[2]) + q.w * (k1.w + e1[3]);
        #pragma unroll
        for (int off = 1; off <= 4; off <<= 1)
            d1 += __shfl_xor_sync(0xffffffffu, d1, off);
        float l1 = d1 * scale;
        float mn = fmaxf(m, l1);
        float c0 = __expf(m - mn);
        float p1 = __expf(l1 - mn);
        s = s * c0 + p1;
        acc[0] = acc[0] * c0 + p1 * (v1.x + e1[0]);
        acc[1] = acc[1] * c0 + p1 * (v1.y + e1[1]);
        acc[2] = acc[2] * c0 + p1 * (v1.z + e1[2]);
        acc[3] = acc[3] * c0 + p1 * (v1.w + e1[3]);
    }
    float inv = 1.f / fmaxf(s, 1e-9f);
    *(float4*)&g_attn[(size_t)node * 128 + d0] =
        make_float4(acc[0] * inv, acc[1] * inv, acc[2] * inv, acc[3] * inv);
}

// ---------------- group pooling ----------------
__global__ void __launch_bounds__(128) pool_scatter_kernel(
    const float* __restrict__ x, const int* __restrict__ grp)
{
    int hit = blockIdx.x;
    int d = threadIdx.x;
    int g = grp[hit];
    float val = g_h[(size_t)hit * 128 + d];
    atomicMaxFloat(&g_gmax[g * 128 + d], val);
    int view = (int)x[(size_t)hit * 25 + 3];
    if (view == 0 || view == 1)
        atomicAdd(&g_gsum[view * N_GROUPS * HID + g * 128 + d], val);
    if (d == 0) {
        atomicAdd(&g_cnt[2 * N_GROUPS + g], 1.f);
        if (view == 0 || view == 1) atomicAdd(&g_cnt[view * N_GROUPS + g], 1.f);
    }
}

__global__ void __launch_bounds__(128) pool_finalize_kernel() {
    int g = blockIdx.x;
    int d = threadIdx.x;
    float cx = g_cnt[g], cy = g_cnt[N_GROUPS + g], ca = g_cnt[2 * N_GROUPS + g];
    float sx = g_gsum[g * 128 + d];
    float sy = g_gsum[N_GROUPS * HID + g * 128 + d];
    float px = sx / fmaxf(cx, 1.f);
    float py = sy / fmaxf(cy, 1.f);
    float hx = (cx > 0.f) ? 1.f : 0.f;
    float hy = (cy > 0.f) ? 1.f : 0.f;
    float sum_feat = px * hx + py * hy;
    float valid = fmaxf(hx + hy, 1.f);
    g_ge[g * 256 + d] = sum_feat / valid;
    g_ge[g * 256 + 128 + d] = (ca > 0.f) ? g_gmax[g * 128 + d] : 0.f;
}

// ---------------- fused pairwise scores + symmetrize + sigmoid + mask ----------------
__global__ void __launch_bounds__(256) scores_final_kernel(
    const float* __restrict__ b1, const float* __restrict__ W2, const float* __restrict__ b2,
    const int* __restrict__ batch, float* __restrict__ out)
{
    __shared__ float sAi[16][129], sBj[16][129], sAj[16][129], sBi[16][129];
    __shared__ float sb1[128], sW2[128];
    __shared__ float s2s[16][17];

    int b = blockIdx.x;
    int bi = 0;
    while (b >= 32 - bi) { b -= 32 - bi; bi++; }
    int bj = bi + b;

    int tx = threadIdx.x & 15, ty = threadIdx.x >> 4;
    int tid = threadIdx.x;
    for (int t = tid; t < 16 * 128; t += 256) {
        int rr = t >> 7, cc = t & 127;
        sAi[rr][cc] = g_Aaf[(bi * 16 + rr) * 128 + cc];
        sAj[rr][cc] = g_Aaf[(bj * 16 + rr) * 128 + cc];
        sBi[rr][cc] = g_Baf[(bi * 16 + rr) * 128 + cc];
        sBj[rr][cc] = g_Baf[(bj * 16 + rr) * 128 + cc];
    }
    if (tid < 128) { sb1[tid] = b1[tid]; sW2[tid] = W2[tid]; }
    __syncthreads();

    float s1 = 0.f, s2 = 0.f;
    #pragma unroll 8
    for (int d = 0; d < 128; d++) {
        float w = sW2[d], bb = sb1[d];
        s1 = fmaf(fmaxf(sAi[ty][d] + sBj[tx][d] + bb, 0.f), w, s1);
        s2 = fmaf(fmaxf(sAj[ty][d] + sBi[tx][d] + bb, 0.f), w, s2);
    }
    s2s[ty][tx] = s2;
    __syncthreads();

    float sc = 0.5f * (s1 + s2s[tx][ty]) + b2[0];
    int i = bi * 16 + ty, j = bj * 16 + tx;
    float mask = (batch[i] == batch[j]) ? 1.f : 0.f;
    float val = mask / (1.f + expf(-sc));
    out[(size_t)i * N_GROUPS + j] = val;
    out[(size_t)j * N_GROUPS + i] = val;
}

// ---------------- launch ----------------
extern "C" void kernel_launch(void* const* d_in, const int* in_sizes, int n_in,
                              void* d_out, int out_size)
{
    const float* x          = (const float*)d_in[0];
    const int*   edge_index = (const int*)  d_in[1];
    const float* edge_attr  = (const float*)d_in[2];
    const int*   grp        = (const int*)  d_in[3];
    const int*   batch      = (const int*)  d_in[4];
    const float* embed_W    = (const float*)d_in[5];
    const float* embed_b    = (const float*)d_in[6];
    const float* Wqkv       = (const float*)d_in[7];
    const float* bqkv       = (const float*)d_in[8];
    const float* We         = (const float*)d_in[9];
    const float* be         = (const float*)d_in[10];
    const float* Wo         = (const float*)d_in[11];
    const float* bo         = (const float*)d_in[12];
    const float* ln1g       = (const float*)d_in[13];
    const float* ln1b       = (const float*)d_in[14];
    const float* W1         = (const float*)d_in[15];
    const float* b1         = (const float*)d_in[16];
    const float* W2         = (const float*)d_in[17];
    const float* b2         = (const float*)d_in[18];
    const float* ln2g       = (const float*)d_in[19];
    const float* ln2b       = (const float*)d_in[20];
    const float* affW1      = (const float*)d_in[21];
    const float* affb1      = (const float*)d_in[22];
    const float* affW2      = (const float*)d_in[23];
    const float* affb2      = (const float*)d_in[24];
    float* out = (float*)d_out;

    float *p_h, *p_qkv, *p_attn, *p_ffn, *p_ge, *p_A, *p_B;
    cudaGetSymbolAddress((void**)&p_h,    g_h);
    cudaGetSymbolAddress((void**)&p_qkv,  g_qkv);
    cudaGetSymbolAddress((void**)&p_attn, g_attn);
    cudaGetSymbolAddress((void**)&p_ffn,  g_ffn);
    cudaGetSymbolAddress((void**)&p_ge,   g_ge);
    cudaGetSymbolAddress((void**)&p_A,    g_Aaf);
    cudaGetSymbolAddress((void**)&p_B,    g_Baf);

    cudaFuncSetAttribute(gemm_kernel, cudaFuncAttributeMaxDynamicSharedMemorySize, GEMM_SMEM);

    // launch index 3 is the ncu-profiled slot -> qkv GEMM there
    embed_kernel<<<N_HITS / 8, 128>>>(x, embed_W, embed_b);                    // 0 (also zeroes buffers)
    hist_kernel<<<N_EDGES / 256, 256>>>(edge_index);                           // 1
    scan_kernel<<<1, 1024>>>();                                                // 2
    gemm_kernel<<<dim3(3, 256), 256, GEMM_SMEM>>>(                             // 3 (profiled)
        p_h, Wqkv, bqkv, p_qkv, N_HITS, 384, 128, 0, nullptr, nullptr, nullptr);
    scatter_kernel<<<N_EDGES / 256, 256>>>(edge_index, edge_attr);             // 4

    for (int l = 0; l < LAYERS; l++) {
        if (l > 0) {
            gemm_kernel<<<dim3(3, 256), 256, GEMM_SMEM>>>(
                p_h, Wqkv + (size_t)l * 49152, bqkv + l * 384, p_qkv,
                N_HITS, 384, 128, 0, nullptr, nullptr, nullptr);
        }
        attn_kernel<<<N_HITS / 8, 256>>>(We + (size_t)l * EDGE_DIM * HID, be + l * HID);
        // h = LN1(h + attn @ Wo + bo)
        gemm_kernel<<<dim3(1, 256), 256, GEMM_SMEM>>>(
            p_attn, Wo + (size_t)l * 16384, bo + l * 128, p_h,
            N_HITS, 128, 128, 2, p_h, ln1g + l * 128, ln1b + l * 128);
        // ffn = relu(h @ W1 + b1)
        gemm_kernel<<<dim3(4, 256), 256, GEMM_SMEM>>>(
            p_h, W1 + (size_t)l * 65536, b1 + l * 512, p_ffn,
            N_HITS, 512, 128, 1, nullptr, nullptr, nullptr);
        // h = LN2(h + ffn @ W2 + b2)
        gemm_kernel<<<dim3(1, 256), 256, GEMM_SMEM>>>(
            p_ffn, W2 + (size_t)l * 65536, b2 + l * 128, p_h,
            N_HITS, 128, 512, 2, p_h, ln2g + l * 128, ln2b + l * 128);
    }

    // pooling -> ge [512, 256]
    pool_scatter_kernel<<<N_HITS, 128>>>(x, grp);
    pool_finalize_kernel<<<N_GROUPS, 128>>>();

    // affinity projections: A = ge @ W1a, B = ge @ W1b
    gemm_kernel<<<dim3(1, 8), 256, GEMM_SMEM>>>(
        p_ge, affW1, nullptr, p_A, N_GROUPS, 128, 256, 0, nullptr, nullptr, nullptr);
    gemm_kernel<<<dim3(1, 8), 256, GEMM_SMEM>>>(
        p_ge, affW1 + (size_t)256 * 128, nullptr, p_B, N_GROUPS, 128, 256, 0, nullptr, nullptr, nullptr);

    // fused symmetric scores + sigmoid + mask
    scores_final_kernel<<<528, 256>>>(affb1, affW2, affb2, batch, out);
}